// round 13
// baseline (speedup 1.0000x reference)
#include <cuda_runtime.h>
#include <cuda_fp16.h>

// out[i,c] = sum_k (neigh[i,k]>=0 ? data[neigh[i,k],c] : 0) * w[k,c]
// N=200000, K=27, C=64.
// Two kernels: (1) convert data fp32 -> fp16 scratch (halves gather bytes),
// (2) gather fp16 rows (128B = 8 uint4), weights fp32, accumulate fp32.
// 8 threads/point (16B = 8 fp16 channels each), QP=2 points/thread, TPB=128.

#define NMAX 200000
#define KK 27
#define CC 64
#define QP 2
#define TPB 128
#define PTSBLK 32      // (TPB/8)*QP ; 200000/32 = 6250 exact
#define NPAD 28

__device__ uint4 g_data16[(size_t)NMAX * 8];   // 25.6 MB fp16 scratch, 16B-aligned

__device__ __forceinline__ __half2 u2h2(unsigned u) {
    __half2 h; *reinterpret_cast<unsigned*>(&h) = u; return h;
}
__device__ __forceinline__ unsigned h22u(__half2 h) {
    unsigned u; *reinterpret_cast<__half2*>(&u) = h; return u;
}

__global__ __launch_bounds__(256)
void convert_kernel(const float4* __restrict__ src, int n8) {
    // n8 = N*C/8 : each thread folds 2 float4 (8 floats) -> 1 uint4 (8 halves)
    uint4* dst = g_data16;
    for (int i = blockIdx.x * 256 + threadIdx.x; i < n8; i += gridDim.x * 256) {
        const float4 v0 = __ldg(src + 2 * i);
        const float4 v1 = __ldg(src + 2 * i + 1);
        uint4 o;
        o.x = h22u(__floats2half2_rn(v0.x, v0.y));
        o.y = h22u(__floats2half2_rn(v0.z, v0.w));
        o.z = h22u(__floats2half2_rn(v1.x, v1.y));
        o.w = h22u(__floats2half2_rn(v1.z, v1.w));
        dst[i] = o;
    }
}

__device__ __forceinline__ void gfma(const uint4 h, const float4 w0, const float4 w1,
                                     float4& al, float4& ah) {
    const float2 f0 = __half22float2(u2h2(h.x));
    const float2 f1 = __half22float2(u2h2(h.y));
    const float2 f2 = __half22float2(u2h2(h.z));
    const float2 f3 = __half22float2(u2h2(h.w));
    al.x = fmaf(f0.x, w0.x, al.x);  al.y = fmaf(f0.y, w0.y, al.y);
    al.z = fmaf(f1.x, w0.z, al.z);  al.w = fmaf(f1.y, w0.w, al.w);
    ah.x = fmaf(f2.x, w1.x, ah.x);  ah.y = fmaf(f2.y, w1.y, ah.y);
    ah.z = fmaf(f3.x, w1.z, ah.z);  ah.w = fmaf(f3.y, w1.w, ah.w);
}

#define GSTEP(K, COMP) \
    { \
        const float4 w0 = __ldg(w4g + (K) * 16 + 2 * lane); \
        const float4 w1 = __ldg(w4g + (K) * 16 + 2 * lane + 1); \
        const int a = i0.COMP, b = i1.COMP; \
        if (a >= 0) { \
            const uint4 h = __ldg(dh + (unsigned)a * 8 + lane); \
            gfma(h, w0, w1, a0l, a0h); \
        } \
        if (b >= 0) { \
            const uint4 h = __ldg(dh + (unsigned)b * 8 + lane); \
            gfma(h, w0, w1, a1l, a1h); \
        } \
    }

__global__ __launch_bounds__(TPB)
void octree_dwconv_kernel(const float4* __restrict__ w4g,     // [27*16] float4
                          const int*    __restrict__ neigh,   // [N][27]
                          float4*       __restrict__ out)     // [N][16]
{
    __shared__ int s_n[PTSBLK * NPAD];    // 32*28*4 = 3584 B

    const int tid  = threadIdx.x;
    const int base = blockIdx.x * PTSBLK;

    #pragma unroll
    for (int i = tid; i < PTSBLK * KK; i += TPB) {
        const int p = i / KK;
        const int k = i - p * KK;
        s_n[p * NPAD + k] = neigh[base * KK + i];
    }
    __syncthreads();

    const int lane = tid & 7;        // 0..7 : 8 fp16 channels (one uint4) each
    const int g    = tid >> 3;       // group 0..15
    const int p0   = g * QP;

    const uint4* __restrict__ dh = g_data16;                 // [N][8] uint4
    const int4* s_n4 = reinterpret_cast<const int4*>(s_n);   // [32][7]

    float4 a0l = make_float4(0.f, 0.f, 0.f, 0.f), a0h = a0l;
    float4 a1l = a0l, a1h = a0l;

    #pragma unroll
    for (int kc = 0; kc < 7; kc++) {
        const int4 i0 = s_n4[(p0 + 0) * 7 + kc];
        const int4 i1 = s_n4[(p0 + 1) * 7 + kc];

        const int kb = kc * 4;
        GSTEP(kb + 0, x)
        GSTEP(kb + 1, y)
        GSTEP(kb + 2, z)
        if (kc < 6) {            // k = 27 doesn't exist (27 = 6*4 + 3)
            GSTEP(kb + 3, w)
        }
    }

    // out row i: thread covers channels [8*lane, 8*lane+8) = float4 slots 2*lane, 2*lane+1
    const unsigned ob = (unsigned)(base + p0) * 16 + 2 * lane;
    out[ob + 0]  = a0l;
    out[ob + 1]  = a0h;
    out[ob + 16] = a1l;
    out[ob + 17] = a1h;
}

extern "C" void kernel_launch(void* const* d_in, const int* in_sizes, int n_in,
                              void* d_out, int out_size) {
    const float4* data    = (const float4*)d_in[0];   // [N,64] fp32
    const float4* w4g     = (const float4*)d_in[1];   // [27,1,64] fp32
    const int*    neigh   = (const int*)d_in[2];      // [N,27] int32
    float4* out = (float4*)d_out;

    const int N  = in_sizes[0] / CC;                  // 200000
    const int n8 = in_sizes[0] / 8;                   // N*C/8 uint4 outputs

    convert_kernel<<<1184, 256>>>(data, n8);

    const int grid = (N + PTSBLK - 1) / PTSBLK;       // 6250
    octree_dwconv_kernel<<<grid, TPB>>>(w4g, neigh, out);
}